// round 3
// baseline (speedup 1.0000x reference)
#include <cuda_runtime.h>
#include <cuda_bf16.h>
#include <math.h>

// Problem constants
#define TT 512
#define BB 64
#define EE 256
#define HH 256      // per-direction hidden
#define GG 1024     // 4*HH
#define KK 13
#define MM (TT*BB)  // 32768

// ---------------- scratch (static device globals; no allocation in launch) ----
__device__ float g_e[(size_t)MM * EE];             // gathered embeddings [m][e], m = t*64+b
__device__ float g_xg[2][(size_t)MM * GG];         // gate preacts [dir][m][gate]
__device__ float g_h[2][(size_t)TT * HH * BB];     // hidden [dir][t][u][b]
__device__ float g_emis[(size_t)MM * KK];          // emissions [t][b][k]
__device__ int   g_cnt[2][TT];                     // per-step sync counters

// ---------------- double-precision activations (round to fp32 at the end) ----
__device__ __forceinline__ double dsigmoid(double x) { return 1.0 / (1.0 + exp(-x)); }

// ---------------- 0: zero sync counters ----------------
__global__ void zero_cnt_kernel() {
    int i = threadIdx.x;
    if (i < 2 * TT) ((int*)g_cnt)[i] = 0;
}

// ---------------- 1: embedding gather ----------------
__global__ __launch_bounds__(256) void gather_emb_kernel(const int* __restrict__ x,
                                                         const float* __restrict__ emb) {
    int gid = blockIdx.x * 256 + threadIdx.x;      // 2,097,152 total
    int m = gid >> 6;                              // row (t*64+b)
    int j = gid & 63;                              // float4 index within 256
    int t = m >> 6;
    int b = m & 63;
    int tok = x[b * TT + t];
    *(float4*)(g_e + (size_t)m * EE + j * 4) =
        *(const float4*)(emb + (size_t)tok * EE + j * 4);
}

// ---------------- 2: input GEMM  xg = fp32(dot_f64) + (b_ih + b_hh) ----------------
__global__ __launch_bounds__(256) void xg_gemm_kernel(
    const float* __restrict__ wf, const float* __restrict__ wb,
    const float* __restrict__ bihf, const float* __restrict__ bhhf,
    const float* __restrict__ bihb, const float* __restrict__ bhhb)
{
    __shared__ float ash[16][64];   // [k][m]
    __shared__ float bsh[16][64];   // [k][n]

    int dir = blockIdx.z;
    const float* W  = dir ? wb : wf;
    const float* B1 = dir ? bihb : bihf;
    const float* B2 = dir ? bhhb : bhhf;
    float* Cout = g_xg[dir];

    int m0 = blockIdx.x * 64;
    int n0 = blockIdx.y * 64;
    int tid = threadIdx.x;
    int tx = tid & 15;        // n-group
    int ty = tid >> 4;        // m-group

    double acc[4][4];
#pragma unroll
    for (int i = 0; i < 4; i++)
#pragma unroll
        for (int j = 0; j < 4; j++) acc[i][j] = 0.0;

    int ml = tid >> 2;        // 0..63
    int kq = tid & 3;         // 0..3 (4 floats each)

    for (int k0 = 0; k0 < EE; k0 += 16) {
        float4 av = *(const float4*)(g_e + (size_t)(m0 + ml) * EE + k0 + kq * 4);
        float4 bv = *(const float4*)(W   + (size_t)(n0 + ml) * EE + k0 + kq * 4);
        ash[kq * 4 + 0][ml] = av.x; ash[kq * 4 + 1][ml] = av.y;
        ash[kq * 4 + 2][ml] = av.z; ash[kq * 4 + 3][ml] = av.w;
        bsh[kq * 4 + 0][ml] = bv.x; bsh[kq * 4 + 1][ml] = bv.y;
        bsh[kq * 4 + 2][ml] = bv.z; bsh[kq * 4 + 3][ml] = bv.w;
        __syncthreads();
#pragma unroll
        for (int kk = 0; kk < 16; kk++) {
            float4 a4 = *(const float4*)&ash[kk][ty * 4];
            float4 b4 = *(const float4*)&bsh[kk][tx * 4];
            double a0 = a4.x, a1 = a4.y, a2 = a4.z, a3 = a4.w;
            double b0 = b4.x, b1 = b4.y, b2 = b4.z, b3 = b4.w;
            acc[0][0] = fma(a0, b0, acc[0][0]); acc[0][1] = fma(a0, b1, acc[0][1]);
            acc[0][2] = fma(a0, b2, acc[0][2]); acc[0][3] = fma(a0, b3, acc[0][3]);
            acc[1][0] = fma(a1, b0, acc[1][0]); acc[1][1] = fma(a1, b1, acc[1][1]);
            acc[1][2] = fma(a1, b2, acc[1][2]); acc[1][3] = fma(a1, b3, acc[1][3]);
            acc[2][0] = fma(a2, b0, acc[2][0]); acc[2][1] = fma(a2, b1, acc[2][1]);
            acc[2][2] = fma(a2, b2, acc[2][2]); acc[2][3] = fma(a2, b3, acc[2][3]);
            acc[3][0] = fma(a3, b0, acc[3][0]); acc[3][1] = fma(a3, b1, acc[3][1]);
            acc[3][2] = fma(a3, b2, acc[3][2]); acc[3][3] = fma(a3, b3, acc[3][3]);
        }
        __syncthreads();
    }

    float bias[4];
#pragma unroll
    for (int j = 0; j < 4; j++) {
        int n = n0 + tx * 4 + j;
        bias[j] = B1[n] + B2[n];
    }
#pragma unroll
    for (int i = 0; i < 4; i++) {
        float4 r;
        r.x = (float)acc[i][0] + bias[0]; r.y = (float)acc[i][1] + bias[1];
        r.z = (float)acc[i][2] + bias[2]; r.w = (float)acc[i][3] + bias[3];
        *(float4*)(Cout + (size_t)(m0 + ty * 4 + i) * GG + n0 + tx * 4) = r;
    }
}

// ---------------- 3: persistent BiLSTM recurrence (fp64 internal, fp32 states) ----
// smem: wsh double[16][256] (32KB) | hsh float[256][64] (64KB) | xsh float[16][64] | csh float[4][64]
#define LSTM_SMEM_BYTES (32768 + 65536 + 4096 + 1024)
__global__ __launch_bounds__(256) void lstm_persist_kernel(const float* __restrict__ wf,
                                                           const float* __restrict__ wb)
{
    extern __shared__ double smd[];
    double* wsh = smd;                                   // [16][256] doubles
    float* hsh = (float*)(smd + 4096);                   // [256][64] floats (h_prev, [u][b])
    float* xsh = hsh + 16384;                            // [16][64]
    float* csh = xsh + 1024;                             // [4][64]

    int tid = threadIdx.x;
    int dir = blockIdx.x >> 6;
    int g   = blockIdx.x & 63;
    const float* W = dir ? wb : wf;
    const float* xg = g_xg[dir];
    float* hbase = g_h[dir];

    // load the 16 W_hh rows for this CTA as doubles: rr = q*4+du -> row q*256 + g*4 + du
    for (int i = tid; i < 1024; i += 256) {      // i indexes groups of 4 floats
        int rr = i >> 6;
        int e4 = i & 63;
        int grow = (rr >> 2) * 256 + g * 4 + (rr & 3);
        float4 v = *(const float4*)(W + (size_t)grow * 256 + e4 * 4);
        wsh[rr * 256 + e4 * 4 + 0] = (double)v.x;
        wsh[rr * 256 + e4 * 4 + 1] = (double)v.y;
        wsh[rr * 256 + e4 * 4 + 2] = (double)v.z;
        wsh[rr * 256 + e4 * 4 + 3] = (double)v.w;
    }
    csh[tid] = 0.f;
    __syncthreads();

    int r2 = tid >> 5;      // 0..7 -> rows r2, r2+8
    int b2 = tid & 31;      // batches b2, b2+32
    int du = tid >> 6;      // activation mapping
    int bb = tid & 63;

    for (int s = 0; s < TT; s++) {
        int t = dir ? (TT - 1 - s) : s;

        // stage this CTA's xg slice: 64 b x 4 q float4s
        {
            int b = tid >> 2, q = tid & 3;
            float4 v = *(const float4*)(xg + (size_t)(t * 64 + b) * GG + q * 256 + g * 4);
            xsh[(q * 4 + 0) * 64 + b] = v.x;
            xsh[(q * 4 + 1) * 64 + b] = v.y;
            xsh[(q * 4 + 2) * 64 + b] = v.z;
            xsh[(q * 4 + 3) * 64 + b] = v.w;
        }

        if (s > 0) {
            if (tid == 0) {
                while (atomicAdd(&g_cnt[dir][s - 1], 0) != 64) { __nanosleep(64); }
            }
            __syncthreads();
            int tp = dir ? (t + 1) : (t - 1);
            const float* hp = hbase + (size_t)tp * (HH * BB);
            for (int i = tid; i < 4096; i += 256)
                *(float4*)(hsh + i * 4) = *(const float4*)(hp + i * 4);
        }
        __syncthreads();

        // dot in fp64 (accumulate from zero; add xg as fp32 afterwards, like ref)
        double d00 = 0.0, d01 = 0.0, d10 = 0.0, d11 = 0.0;
        if (s > 0) {
            const double* w0p = wsh + r2 * 256;
            const double* w1p = wsh + (r2 + 8) * 256;
#pragma unroll 4
            for (int e4 = 0; e4 < 64; e4++) {
                double w00 = w0p[e4 * 4 + 0], w01 = w0p[e4 * 4 + 1];
                double w02 = w0p[e4 * 4 + 2], w03 = w0p[e4 * 4 + 3];
                double w10 = w1p[e4 * 4 + 0], w11 = w1p[e4 * 4 + 1];
                double w12 = w1p[e4 * 4 + 2], w13 = w1p[e4 * 4 + 3];
                const float* hp0 = hsh + e4 * 256 + b2;
                double h0, h1;
                h0 = hp0[0];   h1 = hp0[32];
                d00 = fma(w00, h0, d00); d01 = fma(w00, h1, d01);
                d10 = fma(w10, h0, d10); d11 = fma(w10, h1, d11);
                h0 = hp0[64];  h1 = hp0[96];
                d00 = fma(w01, h0, d00); d01 = fma(w01, h1, d01);
                d10 = fma(w11, h0, d10); d11 = fma(w11, h1, d11);
                h0 = hp0[128]; h1 = hp0[160];
                d00 = fma(w02, h0, d00); d01 = fma(w02, h1, d01);
                d10 = fma(w12, h0, d10); d11 = fma(w12, h1, d11);
                h0 = hp0[192]; h1 = hp0[224];
                d00 = fma(w03, h0, d00); d01 = fma(w03, h1, d01);
                d10 = fma(w13, h0, d10); d11 = fma(w13, h1, d11);
            }
        }
        // fp32 quantization points: dot -> fp32, then fp32 add of xg (ref: g_in + dot)
        float g00 = xsh[r2 * 64 + b2]            + (float)d00;
        float g01 = xsh[r2 * 64 + b2 + 32]       + (float)d01;
        float g10 = xsh[(r2 + 8) * 64 + b2]      + (float)d10;
        float g11 = xsh[(r2 + 8) * 64 + b2 + 32] + (float)d11;
        __syncthreads();
        xsh[r2 * 64 + b2]             = g00;
        xsh[r2 * 64 + b2 + 32]        = g01;
        xsh[(r2 + 8) * 64 + b2]       = g10;
        xsh[(r2 + 8) * 64 + b2 + 32]  = g11;
        __syncthreads();

        // activation (fp64 internal, fp32 state rounding)
        {
            double iv = xsh[(0 + du) * 64 + bb];
            double fv = xsh[(4 + du) * 64 + bb];
            double gv = xsh[(8 + du) * 64 + bb];
            double ov = xsh[(12 + du) * 64 + bb];
            double c = (double)csh[du * 64 + bb];
            float cf = (float)(dsigmoid(fv) * c + dsigmoid(iv) * tanh(gv));  // fp32 c (ref stores fp32)
            float hf = (float)(dsigmoid(ov) * tanh((double)cf));             // fp32 h
            csh[du * 64 + bb] = cf;
            hbase[(size_t)t * (HH * BB) + (g * 4 + du) * 64 + bb] = hf;
        }
        __threadfence();
        __syncthreads();
        if (tid == 0) atomicAdd(&g_cnt[dir][s], 1);
    }
}

// ---------------- 4: emissions = fp32(dot_f64([h_f|h_b], w_out)) + b_out ----------
__global__ __launch_bounds__(256) void emis_kernel(const float* __restrict__ wout,
                                                   const float* __restrict__ bout)
{
    __shared__ float wsh[KK * 512];     // 26,624 B
    int t = blockIdx.x;
    int tid = threadIdx.x;

    for (int i = tid; i < (KK * 512) / 4; i += 256)
        *(float4*)(wsh + i * 4) = *(const float4*)(wout + i * 4);
    __syncthreads();

    int b = tid & 63;
    int kslot = tid >> 6;

    double acc[4];
#pragma unroll
    for (int i = 0; i < 4; i++) acc[i] = 0.0;

    const float* hf = g_h[0] + (size_t)t * (HH * BB);
    const float* hb = g_h[1] + (size_t)t * (HH * BB);

    // forward half first, then backward half (ref dots the concatenated vector serially)
    for (int u = 0; u < HH; u++) {
        double vf = hf[u * 64 + b];
#pragma unroll
        for (int i = 0; i < 4; i++) {
            int k = kslot + 4 * i;
            if (k < KK) acc[i] = fma(vf, (double)wsh[k * 512 + u], acc[i]);
        }
    }
    for (int u = 0; u < HH; u++) {
        double vb = hb[u * 64 + b];
#pragma unroll
        for (int i = 0; i < 4; i++) {
            int k = kslot + 4 * i;
            if (k < KK) acc[i] = fma(vb, (double)wsh[k * 512 + 256 + u], acc[i]);
        }
    }
#pragma unroll
    for (int i = 0; i < 4; i++) {
        int k = kslot + 4 * i;
        if (k < KK) g_emis[((size_t)t * 64 + b) * KK + k] = (float)acc[i] + bout[k];
    }
}

// ---------------- 5: CRF Viterbi + backtrack (pure fp32 adds, ref order) ----------
#define VIT_SMEM_BYTES ((208 + 208 + 169) * 4 + 511 * 16 * 13)
__global__ __launch_bounds__(256) void viterbi_kernel(const float* __restrict__ start_t,
                                                      const float* __restrict__ end_t,
                                                      const float* __restrict__ trans,
                                                      float* __restrict__ out, int out_size)
{
    extern __shared__ float vsm[];
    float* sA = vsm;                 // [16][13]
    float* sB = sA + 208;            // [16][13]
    float* tr = sB + 208;            // [13][13]
    unsigned char* bps = (unsigned char*)(tr + 169);   // [511][16][13]

    int tid = threadIdx.x;
    int k = tid & 15;
    int bl = tid >> 4;
    int b = blockIdx.x * 16 + bl;
    bool act = (k < KK);

    if (tid < 169) tr[tid] = trans[tid];
    if (act) sA[bl * KK + k] = start_t[k] + g_emis[(size_t)b * KK + k];
    __syncthreads();

    float* cur = sA;
    float* nxt = sB;
    for (int t = 1; t < TT; t++) {
        if (act) {
            float em = g_emis[((size_t)t * 64 + b) * KK + k];
            float best = (cur[bl * KK + 0] + tr[0 * KK + k]) + em;
            int arg = 0;
#pragma unroll
            for (int j = 1; j < KK; j++) {
                float v = (cur[bl * KK + j] + tr[j * KK + k]) + em;
                if (v > best) { best = v; arg = j; }
            }
            nxt[bl * KK + k] = best;
            bps[((t - 1) * 16 + bl) * KK + k] = (unsigned char)arg;
        }
        __syncthreads();
        float* tmp = cur; cur = nxt; nxt = tmp;
    }

    if (act) cur[bl * KK + k] += end_t[k];
    __syncthreads();

    if (k == 0) {
        float best = cur[bl * KK + 0];
        int arg = 0;
#pragma unroll
        for (int j = 1; j < KK; j++) {
            float v = cur[bl * KK + j];
            if (v > best) { best = v; arg = j; }
        }
        if (out_size >= MM + BB) out[MM + b] = best;
        int tag = arg;
        out[(size_t)b * TT + (TT - 1)] = (float)tag;
        for (int t = TT - 2; t >= 0; t--) {
            tag = bps[(t * 16 + bl) * KK + tag];
            out[(size_t)b * TT + t] = (float)tag;
        }
    }
}

// ---------------- launch ----------------
extern "C" void kernel_launch(void* const* d_in, const int* in_sizes, int n_in,
                              void* d_out, int out_size)
{
    const int*   x       = (const int*)  d_in[0];
    const float* emb     = (const float*)d_in[1];
    const float* w_ih_f  = (const float*)d_in[2];
    const float* w_hh_f  = (const float*)d_in[3];
    const float* b_ih_f  = (const float*)d_in[4];
    const float* b_hh_f  = (const float*)d_in[5];
    const float* w_ih_b  = (const float*)d_in[6];
    const float* w_hh_b  = (const float*)d_in[7];
    const float* b_ih_b  = (const float*)d_in[8];
    const float* b_hh_b  = (const float*)d_in[9];
    const float* w_out   = (const float*)d_in[10];
    const float* b_out   = (const float*)d_in[11];
    const float* start_t = (const float*)d_in[12];
    const float* end_t   = (const float*)d_in[13];
    const float* trans   = (const float*)d_in[14];
    float* out = (float*)d_out;

    cudaFuncSetAttribute(lstm_persist_kernel,
                         cudaFuncAttributeMaxDynamicSharedMemorySize,
                         LSTM_SMEM_BYTES);
    cudaFuncSetAttribute(viterbi_kernel,
                         cudaFuncAttributeMaxDynamicSharedMemorySize,
                         VIT_SMEM_BYTES);

    zero_cnt_kernel<<<1, 1024>>>();
    gather_emb_kernel<<<8192, 256>>>(x, emb);
    dim3 gg(512, 16, 2);
    xg_gemm_kernel<<<gg, 256>>>(w_ih_f, w_ih_b, b_ih_f, b_hh_f, b_ih_b, b_hh_b);
    lstm_persist_kernel<<<128, 256, LSTM_SMEM_BYTES>>>(w_hh_f, w_hh_b);
    emis_kernel<<<TT, 256>>>(w_out, b_out);
    viterbi_kernel<<<4, 256, VIT_SMEM_BYTES>>>(start_t, end_t, trans, out, out_size);
}

// round 4
// speedup vs baseline: 11.5758x; 11.5758x over previous
#include <cuda_runtime.h>
#include <cuda_bf16.h>
#include <math.h>

// Problem constants
#define TT 512
#define BB 64
#define EE 256
#define HH 256      // per-direction hidden
#define GG 1024     // 4*HH
#define KK 13
#define MM (TT*BB)  // 32768

// ---------------- scratch (static device globals; no allocation in launch) ----
__device__ float g_e[(size_t)MM * EE];             // gathered embeddings [m][e], m = t*64+b
__device__ float g_xg[2][(size_t)MM * GG];         // gate preacts [dir][m][gate]
__device__ float g_h[2][(size_t)TT * HH * BB];     // hidden [dir][t][u][b]
__device__ float g_emis[(size_t)MM * KK];          // emissions [t][b][k]
__device__ int   g_cnt[2][TT];                     // per-step sync counters

// ---------------- double-precision activations (fp32 rounding at state points) ----
__device__ __forceinline__ double dsigmoid(double x) { return 1.0 / (1.0 + exp(-x)); }

// Kahan merge of a chunk-sum p into (acc, comp). Intrinsics -> no reassociation.
#define KMERGE(acc, comp, p) do {                      \
    float _y = __fsub_rn((p), (comp));                 \
    float _t = __fadd_rn((acc), _y);                   \
    (comp) = __fsub_rn(__fsub_rn(_t, (acc)), _y);      \
    (acc) = _t;                                        \
} while (0)

// ---------------- 0: zero sync counters ----------------
__global__ void zero_cnt_kernel() {
    int i = threadIdx.x;
    if (i < 2 * TT) ((int*)g_cnt)[i] = 0;
}

// ---------------- 1: embedding gather ----------------
__global__ __launch_bounds__(256) void gather_emb_kernel(const int* __restrict__ x,
                                                         const float* __restrict__ emb) {
    int gid = blockIdx.x * 256 + threadIdx.x;      // 2,097,152 total
    int m = gid >> 6;                              // row (t*64+b)
    int j = gid & 63;                              // float4 index within 256
    int t = m >> 6;
    int b = m & 63;
    int tok = x[b * TT + t];
    *(float4*)(g_e + (size_t)m * EE + j * 4) =
        *(const float4*)(emb + (size_t)tok * EE + j * 4);
}

// ---------------- 2: input GEMM  xg = kahan_dot + (b_ih + b_hh) ----------------
// 64x64 tile, 256 threads, 4x4 register blocking; 16-term chunk per smem stage,
// Kahan merge per stage per accumulator.
__global__ __launch_bounds__(256) void xg_gemm_kernel(
    const float* __restrict__ wf, const float* __restrict__ wb,
    const float* __restrict__ bihf, const float* __restrict__ bhhf,
    const float* __restrict__ bihb, const float* __restrict__ bhhb)
{
    __shared__ float ash[16][64];   // [k][m]
    __shared__ float bsh[16][64];   // [k][n]

    int dir = blockIdx.z;
    const float* W  = dir ? wb : wf;
    const float* B1 = dir ? bihb : bihf;
    const float* B2 = dir ? bhhb : bhhf;
    float* Cout = g_xg[dir];

    int m0 = blockIdx.x * 64;
    int n0 = blockIdx.y * 64;
    int tid = threadIdx.x;
    int tx = tid & 15;        // n-group
    int ty = tid >> 4;        // m-group

    float acc[4][4], cmp[4][4];
#pragma unroll
    for (int i = 0; i < 4; i++)
#pragma unroll
        for (int j = 0; j < 4; j++) { acc[i][j] = 0.f; cmp[i][j] = 0.f; }

    int ml = tid >> 2;        // 0..63
    int kq = tid & 3;         // 0..3 (4 floats each)

    for (int k0 = 0; k0 < EE; k0 += 16) {
        float4 av = *(const float4*)(g_e + (size_t)(m0 + ml) * EE + k0 + kq * 4);
        float4 bv = *(const float4*)(W   + (size_t)(n0 + ml) * EE + k0 + kq * 4);
        ash[kq * 4 + 0][ml] = av.x; ash[kq * 4 + 1][ml] = av.y;
        ash[kq * 4 + 2][ml] = av.z; ash[kq * 4 + 3][ml] = av.w;
        bsh[kq * 4 + 0][ml] = bv.x; bsh[kq * 4 + 1][ml] = bv.y;
        bsh[kq * 4 + 2][ml] = bv.z; bsh[kq * 4 + 3][ml] = bv.w;
        __syncthreads();

        float part[4][4];
#pragma unroll
        for (int i = 0; i < 4; i++)
#pragma unroll
            for (int j = 0; j < 4; j++) part[i][j] = 0.f;

#pragma unroll
        for (int kk = 0; kk < 16; kk++) {
            float4 a4 = *(const float4*)&ash[kk][ty * 4];
            float4 b4 = *(const float4*)&bsh[kk][tx * 4];
            part[0][0] = __fmaf_rn(a4.x, b4.x, part[0][0]); part[0][1] = __fmaf_rn(a4.x, b4.y, part[0][1]);
            part[0][2] = __fmaf_rn(a4.x, b4.z, part[0][2]); part[0][3] = __fmaf_rn(a4.x, b4.w, part[0][3]);
            part[1][0] = __fmaf_rn(a4.y, b4.x, part[1][0]); part[1][1] = __fmaf_rn(a4.y, b4.y, part[1][1]);
            part[1][2] = __fmaf_rn(a4.y, b4.z, part[1][2]); part[1][3] = __fmaf_rn(a4.y, b4.w, part[1][3]);
            part[2][0] = __fmaf_rn(a4.z, b4.x, part[2][0]); part[2][1] = __fmaf_rn(a4.z, b4.y, part[2][1]);
            part[2][2] = __fmaf_rn(a4.z, b4.z, part[2][2]); part[2][3] = __fmaf_rn(a4.z, b4.w, part[2][3]);
            part[3][0] = __fmaf_rn(a4.w, b4.x, part[3][0]); part[3][1] = __fmaf_rn(a4.w, b4.y, part[3][1]);
            part[3][2] = __fmaf_rn(a4.w, b4.z, part[3][2]); part[3][3] = __fmaf_rn(a4.w, b4.w, part[3][3]);
        }
#pragma unroll
        for (int i = 0; i < 4; i++)
#pragma unroll
            for (int j = 0; j < 4; j++) KMERGE(acc[i][j], cmp[i][j], part[i][j]);
        __syncthreads();
    }

    float bias[4];
#pragma unroll
    for (int j = 0; j < 4; j++) {
        int n = n0 + tx * 4 + j;
        bias[j] = B1[n] + B2[n];
    }
#pragma unroll
    for (int i = 0; i < 4; i++) {
        float4 r;
        r.x = __fsub_rn(acc[i][0], cmp[i][0]) + bias[0];
        r.y = __fsub_rn(acc[i][1], cmp[i][1]) + bias[1];
        r.z = __fsub_rn(acc[i][2], cmp[i][2]) + bias[2];
        r.w = __fsub_rn(acc[i][3], cmp[i][3]) + bias[3];
        *(float4*)(Cout + (size_t)(m0 + ty * 4 + i) * GG + n0 + tx * 4) = r;
    }
}

// ---------------- 3: persistent BiLSTM recurrence (Kahan fp32 dot, fp64 act) ----
// smem: wsh float[16][256] | hsh float[256][64] | xsh float[16][64] | csh float[4][64]
#define LSTM_SMEM_FLOATS (4096 + 16384 + 1024 + 256)
__global__ __launch_bounds__(256) void lstm_persist_kernel(const float* __restrict__ wf,
                                                           const float* __restrict__ wb)
{
    extern __shared__ float sm[];
    float* wsh = sm;                    // [16][256]  gate-row-major
    float* hsh = sm + 4096;             // [256][64]  h_prev, [u][b]
    float* xsh = sm + 4096 + 16384;     // [16][64]   gate preacts / gate results
    float* csh = xsh + 1024;            // [4][64]    cell state

    int tid = threadIdx.x;
    int dir = blockIdx.x >> 6;
    int g   = blockIdx.x & 63;
    const float* W = dir ? wb : wf;
    const float* xg = g_xg[dir];
    float* hbase = g_h[dir];

    // load the 16 W_hh rows for this CTA: rr = q*4+du -> global row q*256 + g*4 + du
    for (int i = tid; i < 1024; i += 256) {      // i = float4 index
        int rr = i >> 6;
        int e4 = i & 63;
        int grow = (rr >> 2) * 256 + g * 4 + (rr & 3);
        *(float4*)(wsh + rr * 256 + e4 * 4) =
            *(const float4*)(W + (size_t)grow * 256 + e4 * 4);
    }
    csh[tid] = 0.f;
    __syncthreads();

    int r2 = tid >> 5;      // 0..7 -> rows r2, r2+8
    int b2 = tid & 31;      // batches b2, b2+32
    int du = tid >> 6;      // activation mapping
    int bb = tid & 63;

    for (int s = 0; s < TT; s++) {
        int t = dir ? (TT - 1 - s) : s;

        // stage this CTA's xg slice: 64 b x 4 q float4s
        {
            int b = tid >> 2, q = tid & 3;
            float4 v = *(const float4*)(xg + (size_t)(t * 64 + b) * GG + q * 256 + g * 4);
            xsh[(q * 4 + 0) * 64 + b] = v.x;
            xsh[(q * 4 + 1) * 64 + b] = v.y;
            xsh[(q * 4 + 2) * 64 + b] = v.z;
            xsh[(q * 4 + 3) * 64 + b] = v.w;
        }

        if (s > 0) {
            if (tid == 0) {
                while (atomicAdd(&g_cnt[dir][s - 1], 0) != 64) { __nanosleep(64); }
            }
            __syncthreads();
            int tp = dir ? (t + 1) : (t - 1);
            const float* hp = hbase + (size_t)tp * (HH * BB);
            for (int i = tid; i < 4096; i += 256)
                *(float4*)(hsh + i * 4) = *(const float4*)(hp + i * 4);
        }
        __syncthreads();

        // Kahan fp32 dot over 256 h-terms: 16 chunks of 16
        float a00 = 0.f, a01 = 0.f, a10 = 0.f, a11 = 0.f;
        float k00 = 0.f, k01 = 0.f, k10 = 0.f, k11 = 0.f;
        if (s > 0) {
            const float* w0p = wsh + r2 * 256;
            const float* w1p = wsh + (r2 + 8) * 256;
#pragma unroll
            for (int e16 = 0; e16 < 16; e16++) {
                float p00 = 0.f, p01 = 0.f, p10 = 0.f, p11 = 0.f;
#pragma unroll
                for (int q = 0; q < 4; q++) {
                    int e4 = e16 * 4 + q;
                    float4 w0 = *(const float4*)(w0p + e4 * 4);
                    float4 w1 = *(const float4*)(w1p + e4 * 4);
                    const float* hp0 = hsh + e4 * 256 + b2;
                    float h0, h1;
                    h0 = hp0[0];   h1 = hp0[32];
                    p00 = __fmaf_rn(w0.x, h0, p00); p01 = __fmaf_rn(w0.x, h1, p01);
                    p10 = __fmaf_rn(w1.x, h0, p10); p11 = __fmaf_rn(w1.x, h1, p11);
                    h0 = hp0[64];  h1 = hp0[96];
                    p00 = __fmaf_rn(w0.y, h0, p00); p01 = __fmaf_rn(w0.y, h1, p01);
                    p10 = __fmaf_rn(w1.y, h0, p10); p11 = __fmaf_rn(w1.y, h1, p11);
                    h0 = hp0[128]; h1 = hp0[160];
                    p00 = __fmaf_rn(w0.z, h0, p00); p01 = __fmaf_rn(w0.z, h1, p01);
                    p10 = __fmaf_rn(w1.z, h0, p10); p11 = __fmaf_rn(w1.z, h1, p11);
                    h0 = hp0[192]; h1 = hp0[224];
                    p00 = __fmaf_rn(w0.w, h0, p00); p01 = __fmaf_rn(w0.w, h1, p01);
                    p10 = __fmaf_rn(w1.w, h0, p10); p11 = __fmaf_rn(w1.w, h1, p11);
                }
                KMERGE(a00, k00, p00); KMERGE(a01, k01, p01);
                KMERGE(a10, k10, p10); KMERGE(a11, k11, p11);
            }
        }
        // fp32 quantization: dot -> fp32, then fp32 add of xg (ref: g_in + dot)
        float g00 = xsh[r2 * 64 + b2]            + __fsub_rn(a00, k00);
        float g01 = xsh[r2 * 64 + b2 + 32]       + __fsub_rn(a01, k01);
        float g10 = xsh[(r2 + 8) * 64 + b2]      + __fsub_rn(a10, k10);
        float g11 = xsh[(r2 + 8) * 64 + b2 + 32] + __fsub_rn(a11, k11);
        __syncthreads();
        xsh[r2 * 64 + b2]             = g00;
        xsh[r2 * 64 + b2 + 32]        = g01;
        xsh[(r2 + 8) * 64 + b2]       = g10;
        xsh[(r2 + 8) * 64 + b2 + 32]  = g11;
        __syncthreads();

        // activation (fp64 internal, fp32 state rounding) — identical to R3
        {
            double iv = xsh[(0 + du) * 64 + bb];
            double fv = xsh[(4 + du) * 64 + bb];
            double gv = xsh[(8 + du) * 64 + bb];
            double ov = xsh[(12 + du) * 64 + bb];
            double c = (double)csh[du * 64 + bb];
            float cf = (float)(dsigmoid(fv) * c + dsigmoid(iv) * tanh(gv));
            float hf = (float)(dsigmoid(ov) * tanh((double)cf));
            csh[du * 64 + bb] = cf;
            hbase[(size_t)t * (HH * BB) + (g * 4 + du) * 64 + bb] = hf;
        }
        __threadfence();
        __syncthreads();
        if (tid == 0) atomicAdd(&g_cnt[dir][s], 1);
    }
}

// ---------------- 4: emissions = kahan_dot([h_f|h_b], w_out) + b_out ----------
__global__ __launch_bounds__(256) void emis_kernel(const float* __restrict__ wout,
                                                   const float* __restrict__ bout)
{
    __shared__ float wsh[KK * 512];     // 26,624 B
    int t = blockIdx.x;
    int tid = threadIdx.x;

    for (int i = tid; i < (KK * 512) / 4; i += 256)
        *(float4*)(wsh + i * 4) = *(const float4*)(wout + i * 4);
    __syncthreads();

    int b = tid & 63;
    int kslot = tid >> 6;

    float acc[4] = {0.f, 0.f, 0.f, 0.f};
    float cmp[4] = {0.f, 0.f, 0.f, 0.f};

    const float* hf = g_h[0] + (size_t)t * (HH * BB);
    const float* hb = g_h[1] + (size_t)t * (HH * BB);

    // forward half then backward half, 16-term chunks
    for (int half = 0; half < 2; half++) {
        const float* hsrc = half ? hb : hf;
        int woff = half ? 256 : 0;
        for (int u0 = 0; u0 < HH; u0 += 16) {
            float part[4] = {0.f, 0.f, 0.f, 0.f};
#pragma unroll
            for (int uu = 0; uu < 16; uu++) {
                float v = hsrc[(u0 + uu) * 64 + b];
#pragma unroll
                for (int i = 0; i < 4; i++) {
                    int k = kslot + 4 * i;
                    if (k < KK)
                        part[i] = __fmaf_rn(v, wsh[k * 512 + woff + u0 + uu], part[i]);
                }
            }
#pragma unroll
            for (int i = 0; i < 4; i++) KMERGE(acc[i], cmp[i], part[i]);
        }
    }
#pragma unroll
    for (int i = 0; i < 4; i++) {
        int k = kslot + 4 * i;
        if (k < KK)
            g_emis[((size_t)t * 64 + b) * KK + k] = __fsub_rn(acc[i], cmp[i]) + bout[k];
    }
}

// ---------------- 5: CRF Viterbi + backtrack (pure fp32 adds, ref order) ----------
#define VIT_SMEM_BYTES ((208 + 208 + 169) * 4 + 511 * 16 * 13)
__global__ __launch_bounds__(256) void viterbi_kernel(const float* __restrict__ start_t,
                                                      const float* __restrict__ end_t,
                                                      const float* __restrict__ trans,
                                                      float* __restrict__ out, int out_size)
{
    extern __shared__ float vsm[];
    float* sA = vsm;                 // [16][13]
    float* sB = sA + 208;            // [16][13]
    float* tr = sB + 208;            // [13][13]
    unsigned char* bps = (unsigned char*)(tr + 169);   // [511][16][13]

    int tid = threadIdx.x;
    int k = tid & 15;
    int bl = tid >> 4;
    int b = blockIdx.x * 16 + bl;
    bool act = (k < KK);

    if (tid < 169) tr[tid] = trans[tid];
    if (act) sA[bl * KK + k] = start_t[k] + g_emis[(size_t)b * KK + k];
    __syncthreads();

    float* cur = sA;
    float* nxt = sB;
    for (int t = 1; t < TT; t++) {
        if (act) {
            float em = g_emis[((size_t)t * 64 + b) * KK + k];
            float best = (cur[bl * KK + 0] + tr[0 * KK + k]) + em;
            int arg = 0;
#pragma unroll
            for (int j = 1; j < KK; j++) {
                float v = (cur[bl * KK + j] + tr[j * KK + k]) + em;
                if (v > best) { best = v; arg = j; }
            }
            nxt[bl * KK + k] = best;
            bps[((t - 1) * 16 + bl) * KK + k] = (unsigned char)arg;
        }
        __syncthreads();
        float* tmp = cur; cur = nxt; nxt = tmp;
    }

    if (act) cur[bl * KK + k] += end_t[k];
    __syncthreads();

    if (k == 0) {
        float best = cur[bl * KK + 0];
        int arg = 0;
#pragma unroll
        for (int j = 1; j < KK; j++) {
            float v = cur[bl * KK + j];
            if (v > best) { best = v; arg = j; }
        }
        if (out_size >= MM + BB) out[MM + b] = best;
        int tag = arg;
        out[(size_t)b * TT + (TT - 1)] = (float)tag;
        for (int t = TT - 2; t >= 0; t--) {
            tag = bps[(t * 16 + bl) * KK + tag];
            out[(size_t)b * TT + t] = (float)tag;
        }
    }
}

// ---------------- launch ----------------
extern "C" void kernel_launch(void* const* d_in, const int* in_sizes, int n_in,
                              void* d_out, int out_size)
{
    const int*   x       = (const int*)  d_in[0];
    const float* emb     = (const float*)d_in[1];
    const float* w_ih_f  = (const float*)d_in[2];
    const float* w_hh_f  = (const float*)d_in[3];
    const float* b_ih_f  = (const float*)d_in[4];
    const float* b_hh_f  = (const float*)d_in[5];
    const float* w_ih_b  = (const float*)d_in[6];
    const float* w_hh_b  = (const float*)d_in[7];
    const float* b_ih_b  = (const float*)d_in[8];
    const float* b_hh_b  = (const float*)d_in[9];
    const float* w_out   = (const float*)d_in[10];
    const float* b_out   = (const float*)d_in[11];
    const float* start_t = (const float*)d_in[12];
    const float* end_t   = (const float*)d_in[13];
    const float* trans   = (const float*)d_in[14];
    float* out = (float*)d_out;

    cudaFuncSetAttribute(lstm_persist_kernel,
                         cudaFuncAttributeMaxDynamicSharedMemorySize,
                         LSTM_SMEM_FLOATS * 4);
    cudaFuncSetAttribute(viterbi_kernel,
                         cudaFuncAttributeMaxDynamicSharedMemorySize,
                         VIT_SMEM_BYTES);

    zero_cnt_kernel<<<1, 1024>>>();
    gather_emb_kernel<<<8192, 256>>>(x, emb);
    dim3 gg(512, 16, 2);
    xg_gemm_kernel<<<gg, 256>>>(w_ih_f, w_ih_b, b_ih_f, b_hh_f, b_ih_b, b_hh_b);
    lstm_persist_kernel<<<128, 256, LSTM_SMEM_FLOATS * 4>>>(w_hh_f, w_hh_b);
    emis_kernel<<<TT, 256>>>(w_out, b_out);
    viterbi_kernel<<<4, 256, VIT_SMEM_BYTES>>>(start_t, end_t, trans, out, out_size);
}

// round 5
// speedup vs baseline: 20.1090x; 1.7372x over previous
#include <cuda_runtime.h>
#include <cuda_bf16.h>
#include <math.h>

// Problem constants
#define TT 512
#define BB 64
#define EE 256
#define HH 256      // per-direction hidden
#define GG 1024     // 4*HH
#define KK 13
#define MM (TT*BB)  // 32768

// ---------------- scratch (static device globals; no allocation in launch) ----
__device__ float g_e[(size_t)MM * EE];             // gathered embeddings [m][e], m = t*64+b
__device__ float g_xg[2][(size_t)MM * GG];         // gate preacts [dir][m][gate]
__device__ float g_h[2][(size_t)TT * HH * BB];     // hidden [dir][t][u][b]
__device__ float g_emis[(size_t)MM * KK];          // emissions [t][b][k]
__device__ int   g_cnt[2][TT];                     // per-step sync counters

// Kahan merge of a chunk-sum p into (acc, comp). Intrinsics -> no reassociation.
#define KMERGE(acc, comp, p) do {                      \
    float _y = __fsub_rn((p), (comp));                 \
    float _t = __fadd_rn((acc), _y);                   \
    (comp) = __fsub_rn(__fsub_rn(_t, (acc)), _y);      \
    (acc) = _t;                                        \
} while (0)

// ---------------- double-single (float,float) helpers -- FFMA pipe only -------
__device__ __forceinline__ float2 two_sum(float a, float b) {
    float s  = __fadd_rn(a, b);
    float bp = __fsub_rn(s, a);
    float e  = __fadd_rn(__fsub_rn(a, __fsub_rn(s, bp)), __fsub_rn(b, bp));
    return make_float2(s, e);
}
__device__ __forceinline__ float2 quick_two_sum(float a, float b) {  // |a| >= |b|
    float s = __fadd_rn(a, b);
    float e = __fsub_rn(b, __fsub_rn(s, a));
    return make_float2(s, e);
}
__device__ __forceinline__ float2 two_prod(float a, float b) {
    float p = __fmul_rn(a, b);
    float e = __fmaf_rn(a, b, -p);
    return make_float2(p, e);
}

// exp(x) as double-single, rel err ~4e-9 (0.04 fp32 ulp). Clamp ±30 covers all
// realistic gate magnitudes; saturation matches fp64->fp32 rounding behavior.
__device__ __forceinline__ float2 exp_ds(float x) {
    x = fmaxf(-30.0f, fminf(30.0f, x));
    float n  = rintf(__fmul_rn(x, 1.4426950408889634f));
    float r1 = __fmaf_rn(n, -0.693359375f, x);            // exact (Cody-Waite hi)
    float2 p = two_prod(n, 2.1219444e-4f);                // n * (c1 - ln2)
    float2 r = two_sum(r1, p.x);
    float rh = r.x;
    float rl = __fadd_rn(r.y, p.y);
    // tail = r^3 * (1/6 + r/24 + r^2/120 + r^3/720 + r^4/5040)  (fp32 is enough)
    float t = 1.9841270e-4f;
    t = __fmaf_rn(t, rh, 1.3888889e-3f);
    t = __fmaf_rn(t, rh, 8.3333333e-3f);
    t = __fmaf_rn(t, rh, 4.1666667e-2f);
    t = __fmaf_rn(t, rh, 1.6666667e-1f);
    float rr   = __fmul_rn(rh, rh);
    float tail = __fmul_rn(__fmul_rn(rr, rh), t);
    tail = __fmaf_rn(rl, __fadd_rn(1.0f, rh), tail);       // first-order rl term
    // ds sum: 1 + rh + rh^2/2 + tail
    float2 h2 = two_prod(rh, rh);
    float hx = __fmul_rn(0.5f, h2.x), hy = __fmul_rn(0.5f, h2.y);  // exact scale
    float2 a  = quick_two_sum(rh, hx);                     // |rh| >= rh^2/2
    float al  = __fadd_rn(a.y, hy);
    float2 b  = two_sum(a.x, tail);
    float bl  = __fadd_rn(b.y, al);
    float2 c  = quick_two_sum(1.0f, b.x);                  // |b.x| <= 0.43
    float cl  = __fadd_rn(c.y, bl);
    float sc  = __int_as_float(((int)n + 127) << 23);      // 2^n, exact
    return make_float2(__fmul_rn(c.x, sc), __fmul_rn(cl, sc));
}

// sigmoid(x) = 1/(1+exp(-x)) in ds (Newton-refined reciprocal)
__device__ __forceinline__ float2 sigmoid_ds(float x) {
    float2 E = exp_ds(-x);
    float2 D = two_sum(1.0f, E.x);
    float Dl = __fadd_rn(D.y, E.y);
    float y  = __frcp_rn(D.x);
    float e  = __fmaf_rn(-D.x, y, 1.0f);
    e        = __fmaf_rn(-Dl, y, e);
    return make_float2(y, __fmul_rn(y, e));
}

// tanh(x) = (E-1)/(E+1), E = exp(2x), residual-corrected division in ds
__device__ __forceinline__ float2 tanh_ds(float x) {
    float2 E = exp_ds(__fmul_rn(2.0f, x));
    float2 num = two_sum(E.x, -1.0f);
    float numl = __fadd_rn(num.y, E.y);
    float2 den = two_sum(E.x, 1.0f);
    float denl = __fadd_rn(den.y, E.y);
    float q  = __fdiv_rn(num.x, den.x);
    float rr = __fmaf_rn(-q, den.x, num.x);
    rr = __fadd_rn(rr, __fmaf_rn(-q, denl, numl));
    float ql = __fmul_rn(rr, __frcp_rn(den.x));
    return make_float2(q, ql);
}

// ---------------- 0: zero sync counters ----------------
__global__ void zero_cnt_kernel() {
    int i = threadIdx.x;
    if (i < 2 * TT) ((int*)g_cnt)[i] = 0;
}

// ---------------- 1: embedding gather ----------------
__global__ __launch_bounds__(256) void gather_emb_kernel(const int* __restrict__ x,
                                                         const float* __restrict__ emb) {
    int gid = blockIdx.x * 256 + threadIdx.x;      // 2,097,152 total
    int m = gid >> 6;                              // row (t*64+b)
    int j = gid & 63;                              // float4 index within 256
    int t = m >> 6;
    int b = m & 63;
    int tok = x[b * TT + t];
    *(float4*)(g_e + (size_t)m * EE + j * 4) =
        *(const float4*)(emb + (size_t)tok * EE + j * 4);
}

// ---------------- 2: input GEMM  xg = kahan_dot + (b_ih + b_hh) ----------------
__global__ __launch_bounds__(256) void xg_gemm_kernel(
    const float* __restrict__ wf, const float* __restrict__ wb,
    const float* __restrict__ bihf, const float* __restrict__ bhhf,
    const float* __restrict__ bihb, const float* __restrict__ bhhb)
{
    __shared__ float ash[16][64];   // [k][m]
    __shared__ float bsh[16][64];   // [k][n]

    int dir = blockIdx.z;
    const float* W  = dir ? wb : wf;
    const float* B1 = dir ? bihb : bihf;
    const float* B2 = dir ? bhhb : bhhf;
    float* Cout = g_xg[dir];

    int m0 = blockIdx.x * 64;
    int n0 = blockIdx.y * 64;
    int tid = threadIdx.x;
    int tx = tid & 15;        // n-group
    int ty = tid >> 4;        // m-group

    float acc[4][4], cmp[4][4];
#pragma unroll
    for (int i = 0; i < 4; i++)
#pragma unroll
        for (int j = 0; j < 4; j++) { acc[i][j] = 0.f; cmp[i][j] = 0.f; }

    int ml = tid >> 2;        // 0..63
    int kq = tid & 3;         // 0..3 (4 floats each)

    for (int k0 = 0; k0 < EE; k0 += 16) {
        float4 av = *(const float4*)(g_e + (size_t)(m0 + ml) * EE + k0 + kq * 4);
        float4 bv = *(const float4*)(W   + (size_t)(n0 + ml) * EE + k0 + kq * 4);
        ash[kq * 4 + 0][ml] = av.x; ash[kq * 4 + 1][ml] = av.y;
        ash[kq * 4 + 2][ml] = av.z; ash[kq * 4 + 3][ml] = av.w;
        bsh[kq * 4 + 0][ml] = bv.x; bsh[kq * 4 + 1][ml] = bv.y;
        bsh[kq * 4 + 2][ml] = bv.z; bsh[kq * 4 + 3][ml] = bv.w;
        __syncthreads();

        float part[4][4];
#pragma unroll
        for (int i = 0; i < 4; i++)
#pragma unroll
            for (int j = 0; j < 4; j++) part[i][j] = 0.f;

#pragma unroll
        for (int kk = 0; kk < 16; kk++) {
            float4 a4 = *(const float4*)&ash[kk][ty * 4];
            float4 b4 = *(const float4*)&bsh[kk][tx * 4];
            part[0][0] = __fmaf_rn(a4.x, b4.x, part[0][0]); part[0][1] = __fmaf_rn(a4.x, b4.y, part[0][1]);
            part[0][2] = __fmaf_rn(a4.x, b4.z, part[0][2]); part[0][3] = __fmaf_rn(a4.x, b4.w, part[0][3]);
            part[1][0] = __fmaf_rn(a4.y, b4.x, part[1][0]); part[1][1] = __fmaf_rn(a4.y, b4.y, part[1][1]);
            part[1][2] = __fmaf_rn(a4.y, b4.z, part[1][2]); part[1][3] = __fmaf_rn(a4.y, b4.w, part[1][3]);
            part[2][0] = __fmaf_rn(a4.z, b4.x, part[2][0]); part[2][1] = __fmaf_rn(a4.z, b4.y, part[2][1]);
            part[2][2] = __fmaf_rn(a4.z, b4.z, part[2][2]); part[2][3] = __fmaf_rn(a4.z, b4.w, part[2][3]);
            part[3][0] = __fmaf_rn(a4.w, b4.x, part[3][0]); part[3][1] = __fmaf_rn(a4.w, b4.y, part[3][1]);
            part[3][2] = __fmaf_rn(a4.w, b4.z, part[3][2]); part[3][3] = __fmaf_rn(a4.w, b4.w, part[3][3]);
        }
#pragma unroll
        for (int i = 0; i < 4; i++)
#pragma unroll
            for (int j = 0; j < 4; j++) KMERGE(acc[i][j], cmp[i][j], part[i][j]);
        __syncthreads();
    }

    float bias[4];
#pragma unroll
    for (int j = 0; j < 4; j++) {
        int n = n0 + tx * 4 + j;
        bias[j] = B1[n] + B2[n];
    }
#pragma unroll
    for (int i = 0; i < 4; i++) {
        float4 r;
        r.x = __fsub_rn(acc[i][0], cmp[i][0]) + bias[0];
        r.y = __fsub_rn(acc[i][1], cmp[i][1]) + bias[1];
        r.z = __fsub_rn(acc[i][2], cmp[i][2]) + bias[2];
        r.w = __fsub_rn(acc[i][3], cmp[i][3]) + bias[3];
        *(float4*)(Cout + (size_t)(m0 + ty * 4 + i) * GG + n0 + tx * 4) = r;
    }
}

// ---------------- 3: persistent BiLSTM recurrence (Kahan fp32 dot, ds act) ----
#define LSTM_SMEM_FLOATS (4096 + 16384 + 1024 + 256)
__global__ __launch_bounds__(256) void lstm_persist_kernel(const float* __restrict__ wf,
                                                           const float* __restrict__ wb)
{
    extern __shared__ float sm[];
    float* wsh = sm;                    // [16][256]  gate-row-major
    float* hsh = sm + 4096;             // [256][64]  h_prev, [u][b]
    float* xsh = sm + 4096 + 16384;     // [16][64]   gate preacts / gate results
    float* csh = xsh + 1024;            // [4][64]    cell state

    int tid = threadIdx.x;
    int dir = blockIdx.x >> 6;
    int g   = blockIdx.x & 63;
    const float* W = dir ? wb : wf;
    const float* xg = g_xg[dir];
    float* hbase = g_h[dir];

    // load the 16 W_hh rows for this CTA: rr = q*4+du -> global row q*256 + g*4 + du
    for (int i = tid; i < 1024; i += 256) {      // i = float4 index
        int rr = i >> 6;
        int e4 = i & 63;
        int grow = (rr >> 2) * 256 + g * 4 + (rr & 3);
        *(float4*)(wsh + rr * 256 + e4 * 4) =
            *(const float4*)(W + (size_t)grow * 256 + e4 * 4);
    }
    csh[tid] = 0.f;
    __syncthreads();

    int r2 = tid >> 5;      // 0..7 -> rows r2, r2+8
    int b2 = tid & 31;      // batches b2, b2+32
    int du = tid >> 6;      // activation mapping
    int bb = tid & 63;

    for (int s = 0; s < TT; s++) {
        int t = dir ? (TT - 1 - s) : s;

        // stage this CTA's xg slice: 64 b x 4 q float4s
        {
            int b = tid >> 2, q = tid & 3;
            float4 v = *(const float4*)(xg + (size_t)(t * 64 + b) * GG + q * 256 + g * 4);
            xsh[(q * 4 + 0) * 64 + b] = v.x;
            xsh[(q * 4 + 1) * 64 + b] = v.y;
            xsh[(q * 4 + 2) * 64 + b] = v.z;
            xsh[(q * 4 + 3) * 64 + b] = v.w;
        }

        if (s > 0) {
            if (tid == 0) {
                while (atomicAdd(&g_cnt[dir][s - 1], 0) != 64) { __nanosleep(64); }
            }
            __syncthreads();
            int tp = dir ? (t + 1) : (t - 1);
            const float* hp = hbase + (size_t)tp * (HH * BB);
            for (int i = tid; i < 4096; i += 256)
                *(float4*)(hsh + i * 4) = *(const float4*)(hp + i * 4);
        }
        __syncthreads();

        // Kahan fp32 dot over 256 h-terms: 16 chunks of 16
        float a00 = 0.f, a01 = 0.f, a10 = 0.f, a11 = 0.f;
        float k00 = 0.f, k01 = 0.f, k10 = 0.f, k11 = 0.f;
        if (s > 0) {
            const float* w0p = wsh + r2 * 256;
            const float* w1p = wsh + (r2 + 8) * 256;
#pragma unroll
            for (int e16 = 0; e16 < 16; e16++) {
                float p00 = 0.f, p01 = 0.f, p10 = 0.f, p11 = 0.f;
#pragma unroll
                for (int q = 0; q < 4; q++) {
                    int e4 = e16 * 4 + q;
                    float4 w0 = *(const float4*)(w0p + e4 * 4);
                    float4 w1 = *(const float4*)(w1p + e4 * 4);
                    const float* hp0 = hsh + e4 * 256 + b2;
                    float h0, h1;
                    h0 = hp0[0];   h1 = hp0[32];
                    p00 = __fmaf_rn(w0.x, h0, p00); p01 = __fmaf_rn(w0.x, h1, p01);
                    p10 = __fmaf_rn(w1.x, h0, p10); p11 = __fmaf_rn(w1.x, h1, p11);
                    h0 = hp0[64];  h1 = hp0[96];
                    p00 = __fmaf_rn(w0.y, h0, p00); p01 = __fmaf_rn(w0.y, h1, p01);
                    p10 = __fmaf_rn(w1.y, h0, p10); p11 = __fmaf_rn(w1.y, h1, p11);
                    h0 = hp0[128]; h1 = hp0[160];
                    p00 = __fmaf_rn(w0.z, h0, p00); p01 = __fmaf_rn(w0.z, h1, p01);
                    p10 = __fmaf_rn(w1.z, h0, p10); p11 = __fmaf_rn(w1.z, h1, p11);
                    h0 = hp0[192]; h1 = hp0[224];
                    p00 = __fmaf_rn(w0.w, h0, p00); p01 = __fmaf_rn(w0.w, h1, p01);
                    p10 = __fmaf_rn(w1.w, h0, p10); p11 = __fmaf_rn(w1.w, h1, p11);
                }
                KMERGE(a00, k00, p00); KMERGE(a01, k01, p01);
                KMERGE(a10, k10, p10); KMERGE(a11, k11, p11);
            }
        }
        // fp32 quantization: dot -> fp32, then fp32 add of xg (ref: g_in + dot)
        float g00 = xsh[r2 * 64 + b2]            + __fsub_rn(a00, k00);
        float g01 = xsh[r2 * 64 + b2 + 32]       + __fsub_rn(a01, k01);
        float g10 = xsh[(r2 + 8) * 64 + b2]      + __fsub_rn(a10, k10);
        float g11 = xsh[(r2 + 8) * 64 + b2 + 32] + __fsub_rn(a11, k11);
        __syncthreads();
        xsh[r2 * 64 + b2]             = g00;
        xsh[r2 * 64 + b2 + 32]        = g01;
        xsh[(r2 + 8) * 64 + b2]       = g10;
        xsh[(r2 + 8) * 64 + b2 + 32]  = g11;
        __syncthreads();

        // activation in double-single on the FFMA pipe (quantize at c and h only)
        {
            float iv = xsh[(0 + du) * 64 + bb];
            float fv = xsh[(4 + du) * 64 + bb];
            float gv = xsh[(8 + du) * 64 + bb];
            float ov = xsh[(12 + du) * 64 + bb];
            float c  = csh[du * 64 + bb];

            float2 sf = sigmoid_ds(fv);
            float2 si = sigmoid_ds(iv);
            float2 tg = tanh_ds(gv);
            // p1 = sf * c
            float2 p1 = two_prod(sf.x, c);
            float p1l = __fmaf_rn(sf.y, c, p1.y);
            // p2 = si * tg
            float2 p2 = two_prod(si.x, tg.x);
            float p2l = __fmaf_rn(si.x, tg.y, __fmaf_rn(si.y, tg.x, p2.y));
            float2 sck = two_sum(p1.x, p2.x);
            float cf = __fadd_rn(sck.x, __fadd_rn(sck.y, __fadd_rn(p1l, p2l)));

            float2 so = sigmoid_ds(ov);
            float2 tc = tanh_ds(cf);
            float2 ph = two_prod(so.x, tc.x);
            float phl = __fmaf_rn(so.x, tc.y, __fmaf_rn(so.y, tc.x, ph.y));
            float hf = __fadd_rn(ph.x, phl);

            csh[du * 64 + bb] = cf;
            hbase[(size_t)t * (HH * BB) + (g * 4 + du) * 64 + bb] = hf;
        }
        __threadfence();
        __syncthreads();
        if (tid == 0) atomicAdd(&g_cnt[dir][s], 1);
    }
}

// ---------------- 4: emissions = kahan_dot([h_f|h_b], w_out) + b_out ----------
__global__ __launch_bounds__(256) void emis_kernel(const float* __restrict__ wout,
                                                   const float* __restrict__ bout)
{
    __shared__ float wsh[KK * 512];     // 26,624 B
    int t = blockIdx.x;
    int tid = threadIdx.x;

    for (int i = tid; i < (KK * 512) / 4; i += 256)
        *(float4*)(wsh + i * 4) = *(const float4*)(wout + i * 4);
    __syncthreads();

    int b = tid & 63;
    int kslot = tid >> 6;

    float acc[4] = {0.f, 0.f, 0.f, 0.f};
    float cmp[4] = {0.f, 0.f, 0.f, 0.f};

    const float* hf = g_h[0] + (size_t)t * (HH * BB);
    const float* hb = g_h[1] + (size_t)t * (HH * BB);

    for (int half = 0; half < 2; half++) {
        const float* hsrc = half ? hb : hf;
        int woff = half ? 256 : 0;
        for (int u0 = 0; u0 < HH; u0 += 16) {
            float part[4] = {0.f, 0.f, 0.f, 0.f};
#pragma unroll
            for (int uu = 0; uu < 16; uu++) {
                float v = hsrc[(u0 + uu) * 64 + b];
#pragma unroll
                for (int i = 0; i < 4; i++) {
                    int k = kslot + 4 * i;
                    if (k < KK)
                        part[i] = __fmaf_rn(v, wsh[k * 512 + woff + u0 + uu], part[i]);
                }
            }
#pragma unroll
            for (int i = 0; i < 4; i++) KMERGE(acc[i], cmp[i], part[i]);
        }
    }
#pragma unroll
    for (int i = 0; i < 4; i++) {
        int k = kslot + 4 * i;
        if (k < KK)
            g_emis[((size_t)t * 64 + b) * KK + k] = __fsub_rn(acc[i], cmp[i]) + bout[k];
    }
}

// ---------------- 5: CRF Viterbi + backtrack (pure fp32 adds, ref order) ----------
#define VIT_SMEM_BYTES ((208 + 208 + 169) * 4 + 511 * 16 * 13)
__global__ __launch_bounds__(256) void viterbi_kernel(const float* __restrict__ start_t,
                                                      const float* __restrict__ end_t,
                                                      const float* __restrict__ trans,
                                                      float* __restrict__ out, int out_size)
{
    extern __shared__ float vsm[];
    float* sA = vsm;                 // [16][13]
    float* sB = sA + 208;            // [16][13]
    float* tr = sB + 208;            // [13][13]
    unsigned char* bps = (unsigned char*)(tr + 169);   // [511][16][13]

    int tid = threadIdx.x;
    int k = tid & 15;
    int bl = tid >> 4;
    int b = blockIdx.x * 16 + bl;
    bool act = (k < KK);

    if (tid < 169) tr[tid] = trans[tid];
    if (act) sA[bl * KK + k] = start_t[k] + g_emis[(size_t)b * KK + k];
    __syncthreads();

    float* cur = sA;
    float* nxt = sB;
    for (int t = 1; t < TT; t++) {
        if (act) {
            float em = g_emis[((size_t)t * 64 + b) * KK + k];
            float best = (cur[bl * KK + 0] + tr[0 * KK + k]) + em;
            int arg = 0;
#pragma unroll
            for (int j = 1; j < KK; j++) {
                float v = (cur[bl * KK + j] + tr[j * KK + k]) + em;
                if (v > best) { best = v; arg = j; }
            }
            nxt[bl * KK + k] = best;
            bps[((t - 1) * 16 + bl) * KK + k] = (unsigned char)arg;
        }
        __syncthreads();
        float* tmp = cur; cur = nxt; nxt = tmp;
    }

    if (act) cur[bl * KK + k] += end_t[k];
    __syncthreads();

    if (k == 0) {
        float best = cur[bl * KK + 0];
        int arg = 0;
#pragma unroll
        for (int j = 1; j < KK; j++) {
            float v = cur[bl * KK + j];
            if (v > best) { best = v; arg = j; }
        }
        if (out_size >= MM + BB) out[MM + b] = best;
        int tag = arg;
        out[(size_t)b * TT + (TT - 1)] = (float)tag;
        for (int t = TT - 2; t >= 0; t--) {
            tag = bps[(t * 16 + bl) * KK + tag];
            out[(size_t)b * TT + t] = (float)tag;
        }
    }
}

// ---------------- launch ----------------
extern "C" void kernel_launch(void* const* d_in, const int* in_sizes, int n_in,
                              void* d_out, int out_size)
{
    const int*   x       = (const int*)  d_in[0];
    const float* emb     = (const float*)d_in[1];
    const float* w_ih_f  = (const float*)d_in[2];
    const float* w_hh_f  = (const float*)d_in[3];
    const float* b_ih_f  = (const float*)d_in[4];
    const float* b_hh_f  = (const float*)d_in[5];
    const float* w_ih_b  = (const float*)d_in[6];
    const float* w_hh_b  = (const float*)d_in[7];
    const float* b_ih_b  = (const float*)d_in[8];
    const float* b_hh_b  = (const float*)d_in[9];
    const float* w_out   = (const float*)d_in[10];
    const float* b_out   = (const float*)d_in[11];
    const float* start_t = (const float*)d_in[12];
    const float* end_t   = (const float*)d_in[13];
    const float* trans   = (const float*)d_in[14];
    float* out = (float*)d_out;

    cudaFuncSetAttribute(lstm_persist_kernel,
                         cudaFuncAttributeMaxDynamicSharedMemorySize,
                         LSTM_SMEM_FLOATS * 4);
    cudaFuncSetAttribute(viterbi_kernel,
                         cudaFuncAttributeMaxDynamicSharedMemorySize,
                         VIT_SMEM_BYTES);

    zero_cnt_kernel<<<1, 1024>>>();
    gather_emb_kernel<<<8192, 256>>>(x, emb);
    dim3 gg(512, 16, 2);
    xg_gemm_kernel<<<gg, 256>>>(w_ih_f, w_ih_b, b_ih_f, b_hh_f, b_ih_b, b_hh_b);
    lstm_persist_kernel<<<128, 256, LSTM_SMEM_FLOATS * 4>>>(w_hh_f, w_hh_b);
    emis_kernel<<<TT, 256>>>(w_out, b_out);
    viterbi_kernel<<<4, 256, VIT_SMEM_BYTES>>>(start_t, end_t, trans, out, out_size);
}